// round 1
// baseline (speedup 1.0000x reference)
#include <cuda_runtime.h>

#define T_SEQ 2048
#define BATCH 4
#define NFEAT 512
#define HEADS 8
#define DK 64
#define BHTOT (BATCH*HEADS)      // 32
#define MTOT  (BATCH*T_SEQ)      // 8192

// Scratch (static device globals; no runtime allocation allowed)
__device__ float g_q[(size_t)BHTOT*T_SEQ*DK];   // [bh][t][d]  16 MB
__device__ float g_k[(size_t)BHTOT*T_SEQ*DK];
__device__ float g_v[(size_t)BHTOT*T_SEQ*DK];
__device__ float g_x[(size_t)MTOT*NFEAT];       // merged-head attn output [b*T+t][512]

// ---------------------------------------------------------------------------
// GEMM: Out[M,N] = X[M,K] @ W[N,K]^T + bias ; M=8192, N=K=512
// 64x64 block tile, 256 threads, 4x4 per thread, k-chunk 32.
// out_sel: 0 -> Out ptr (plain [m][n]); 1/2/3 -> g_q/g_k/g_v ([bh][t][d] scatter)
// in_sel:  0 -> X ptr; 1 -> g_x
// ---------------------------------------------------------------------------
__global__ __launch_bounds__(256) void gemm_kernel(
    const float* __restrict__ X, const float* __restrict__ W,
    const float* __restrict__ Bv, float* __restrict__ Out,
    int out_sel, int in_sel)
{
    if (in_sel) X = g_x;
    float* O = Out;
    if (out_sel == 1) O = g_q;
    else if (out_sel == 2) O = g_k;
    else if (out_sel == 3) O = g_v;

    __shared__ float At[32][68];   // At[k][m]  (transposed for LDS.128 over m)
    __shared__ float Bt[32][68];   // Bt[k][n]

    const int tid = threadIdx.x;
    const int tx = tid & 15, ty = tid >> 4;
    const int m0 = blockIdx.y * 64;
    const int n0 = blockIdx.x * 64;

    float acc[4][4] = {};

    for (int k0 = 0; k0 < NFEAT; k0 += 32) {
        __syncthreads();
        #pragma unroll
        for (int l = 0; l < 2; l++) {
            int idx = tid + l * 256;         // 0..511 covers 64x8 float4
            int mm  = idx >> 3;              // 0..63
            int kk  = (idx & 7) << 2;        // 0..28
            float4 a = *(const float4*)&X[(size_t)(m0 + mm) * NFEAT + k0 + kk];
            At[kk+0][mm] = a.x; At[kk+1][mm] = a.y; At[kk+2][mm] = a.z; At[kk+3][mm] = a.w;
            float4 b = *(const float4*)&W[(size_t)(n0 + mm) * NFEAT + k0 + kk];
            Bt[kk+0][mm] = b.x; Bt[kk+1][mm] = b.y; Bt[kk+2][mm] = b.z; Bt[kk+3][mm] = b.w;
        }
        __syncthreads();

        #pragma unroll 8
        for (int k = 0; k < 32; k++) {
            float4 a = *(const float4*)&At[k][ty * 4];
            float4 b = *(const float4*)&Bt[k][tx * 4];
            float av[4] = {a.x, a.y, a.z, a.w};
            float bw[4] = {b.x, b.y, b.z, b.w};
            #pragma unroll
            for (int r = 0; r < 4; r++)
                #pragma unroll
                for (int c = 0; c < 4; c++)
                    acc[r][c] = fmaf(av[r], bw[c], acc[r][c]);
        }
    }

    float4 bias = *(const float4*)&Bv[n0 + tx * 4];
    float bb[4] = {bias.x, bias.y, bias.z, bias.w};

    if (out_sel != 0) {
        // scatter to [bh][t][d]: n = h*64 + d; tile never crosses head boundary
        int h  = n0 >> 6;
        int dd = tx * 4;
        #pragma unroll
        for (int r = 0; r < 4; r++) {
            int m = m0 + ty * 4 + r;
            int b = m >> 11, t = m & (T_SEQ - 1);
            float4 o;
            o.x = acc[r][0] + bb[0]; o.y = acc[r][1] + bb[1];
            o.z = acc[r][2] + bb[2]; o.w = acc[r][3] + bb[3];
            *(float4*)&O[((size_t)(b * HEADS + h) * T_SEQ + t) * DK + dd] = o;
        }
    } else {
        #pragma unroll
        for (int r = 0; r < 4; r++) {
            int m = m0 + ty * 4 + r;
            float4 o;
            o.x = acc[r][0] + bb[0]; o.y = acc[r][1] + bb[1];
            o.z = acc[r][2] + bb[2]; o.w = acc[r][3] + bb[3];
            *(float4*)&O[(size_t)m * NFEAT + n0 + tx * 4] = o;
        }
    }
}

// ---------------------------------------------------------------------------
// Flash attention: one block = one (bh, 64-query tile). 256 threads, 4x4/thr.
// Online softmax over 2048 keys in 64-wide tiles. Exact reference semantics:
// masked scores -> excluded; p = softmax / (sum + EPS) == exp/(l*(1+eps)).
// ---------------------------------------------------------------------------
__global__ __launch_bounds__(256) void attn_kernel(const int* __restrict__ mask)
{
    extern __shared__ float sm[];
    float* Qt = sm;                 // Qt[d][row]  stride 68
    float* Kt = sm + 64 * 68;       // Kt[d][col]  -> reused as Pt[j][row]
    float* Vs = sm + 2 * 64 * 68;   // Vs[j][d]    stride 68

    const int tid = threadIdx.x;
    const int tx = tid & 15, ty = tid >> 4;
    const int bh = blockIdx.y;
    const int b  = bh >> 3;
    const int h  = bh & 7;
    const int q0 = blockIdx.x * 64;

    const float* Q = g_q + (size_t)bh * T_SEQ * DK;
    const float* K = g_k + (size_t)bh * T_SEQ * DK;
    const float* V = g_v + (size_t)bh * T_SEQ * DK;

    // Load Q tile transposed (once)
    #pragma unroll
    for (int l = 0; l < 4; l++) {
        int idx = tid + l * 256;            // 1024 float4 = 64 rows x 16
        int r   = idx >> 4;
        int d4  = (idx & 15) << 2;
        float4 a = *(const float4*)&Q[(size_t)(q0 + r) * DK + d4];
        Qt[(d4+0)*68 + r] = a.x; Qt[(d4+1)*68 + r] = a.y;
        Qt[(d4+2)*68 + r] = a.z; Qt[(d4+3)*68 + r] = a.w;
    }

    float acc[4][4] = {};
    float mrow[4] = {-1e30f, -1e30f, -1e30f, -1e30f};
    float lrow[4] = {0.f, 0.f, 0.f, 0.f};

    for (int kt = 0; kt < T_SEQ; kt += 64) {
        __syncthreads();   // previous PV done with Kt(=Pt)/Vs
        #pragma unroll
        for (int l = 0; l < 4; l++) {
            int idx = tid + l * 256;
            int j   = idx >> 4;
            int d4  = (idx & 15) << 2;
            float4 a = *(const float4*)&K[(size_t)(kt + j) * DK + d4];
            Kt[(d4+0)*68 + j] = a.x; Kt[(d4+1)*68 + j] = a.y;
            Kt[(d4+2)*68 + j] = a.z; Kt[(d4+3)*68 + j] = a.w;
            float4 vv = *(const float4*)&V[(size_t)(kt + j) * DK + d4];
            *(float4*)&Vs[j * 68 + d4] = vv;
        }
        __syncthreads();

        // S = Q K^T (64x64, inner 64)
        float s[4][4] = {};
        #pragma unroll 4
        for (int d = 0; d < 64; d++) {
            float4 a = *(const float4*)&Qt[d * 68 + ty * 4];
            float4 bq = *(const float4*)&Kt[d * 68 + tx * 4];
            float av[4] = {a.x, a.y, a.z, a.w};
            float bw[4] = {bq.x, bq.y, bq.z, bq.w};
            #pragma unroll
            for (int r = 0; r < 4; r++)
                #pragma unroll
                for (int c = 0; c < 4; c++)
                    s[r][c] = fmaf(av[r], bw[c], s[r][c]);
        }

        // scale + mask
        float mf[4];
        #pragma unroll
        for (int c = 0; c < 4; c++)
            mf[c] = (float)mask[b * T_SEQ + kt + tx * 4 + c];
        #pragma unroll
        for (int r = 0; r < 4; r++)
            #pragma unroll
            for (int c = 0; c < 4; c++)
                s[r][c] = (mf[c] != 0.f) ? s[r][c] * 0.125f : -1e30f;

        // online softmax (row spread across 16 tx lanes within warp halves)
        float p[4][4];
        float alpha[4];
        #pragma unroll
        for (int r = 0; r < 4; r++) {
            float tm = fmaxf(fmaxf(s[r][0], s[r][1]), fmaxf(s[r][2], s[r][3]));
            #pragma unroll
            for (int o = 1; o < 16; o <<= 1)
                tm = fmaxf(tm, __shfl_xor_sync(0xffffffffu, tm, o));
            float nm = fmaxf(mrow[r], tm);
            float rs = 0.f;
            #pragma unroll
            for (int c = 0; c < 4; c++) {
                float e = __expf(s[r][c] - nm) * mf[c];
                p[r][c] = e;
                rs += e;
            }
            #pragma unroll
            for (int o = 1; o < 16; o <<= 1)
                rs += __shfl_xor_sync(0xffffffffu, rs, o);
            alpha[r] = __expf(mrow[r] - nm);
            lrow[r]  = lrow[r] * alpha[r] + rs;
            mrow[r]  = nm;
        }
        #pragma unroll
        for (int r = 0; r < 4; r++)
            #pragma unroll
            for (int c = 0; c < 4; c++)
                acc[r][c] *= alpha[r];

        __syncthreads();   // all lanes done reading Kt before overwrite with P
        #pragma unroll
        for (int r = 0; r < 4; r++)
            #pragma unroll
            for (int c = 0; c < 4; c++)
                Kt[(tx * 4 + c) * 68 + ty * 4 + r] = p[r][c];   // Pt[j][row]
        __syncthreads();

        // acc += P V
        #pragma unroll 4
        for (int j = 0; j < 64; j++) {
            float4 a  = *(const float4*)&Kt[j * 68 + ty * 4];   // P[j][rows]
            float4 vv = *(const float4*)&Vs[j * 68 + tx * 4];   // V[j][dcols]
            float av[4] = {a.x, a.y, a.z, a.w};
            float bw[4] = {vv.x, vv.y, vv.z, vv.w};
            #pragma unroll
            for (int r = 0; r < 4; r++)
                #pragma unroll
                for (int c = 0; c < 4; c++)
                    acc[r][c] = fmaf(av[r], bw[c], acc[r][c]);
        }
    }

    // epilogue: x = acc / (l * (1 + EPS)); write merged-head layout
    #pragma unroll
    for (int r = 0; r < 4; r++) {
        float denom = lrow[r] * (1.0f + 1e-8f);
        float inv = (denom > 0.f) ? 1.0f / denom : 0.f;
        int q = q0 + ty * 4 + r;
        float4 o;
        o.x = acc[r][0] * inv; o.y = acc[r][1] * inv;
        o.z = acc[r][2] * inv; o.w = acc[r][3] * inv;
        *(float4*)&g_x[((size_t)(b * T_SEQ + q)) * NFEAT + h * DK + tx * 4] = o;
    }
}

// ---------------------------------------------------------------------------
// kernel_launch: 3 projections -> flash attention -> output projection
// ---------------------------------------------------------------------------
extern "C" void kernel_launch(void* const* d_in, const int* in_sizes, int n_in,
                              void* d_out, int out_size)
{
    const float* query = (const float*)d_in[0];
    const float* key_  = (const float*)d_in[1];
    const float* value = (const float*)d_in[2];
    const int*   mask  = (const int*)d_in[3];
    const float* Wq = (const float*)d_in[4];
    const float* bq = (const float*)d_in[5];
    const float* Wk = (const float*)d_in[6];
    const float* bk = (const float*)d_in[7];
    const float* Wv = (const float*)d_in[8];
    const float* bv = (const float*)d_in[9];
    const float* Wo = (const float*)d_in[10];
    const float* bo = (const float*)d_in[11];
    float* out = (float*)d_out;

    dim3 gg(NFEAT / 64, MTOT / 64);   // (8, 128)

    gemm_kernel<<<gg, 256>>>(query, Wq, bq, nullptr, 1, 0);
    gemm_kernel<<<gg, 256>>>(key_,  Wk, bk, nullptr, 2, 0);
    gemm_kernel<<<gg, 256>>>(value, Wv, bv, nullptr, 3, 0);

    const int attn_smem = 3 * 64 * 68 * (int)sizeof(float);   // 52224 B
    cudaFuncSetAttribute(attn_kernel,
                         cudaFuncAttributeMaxDynamicSharedMemorySize, attn_smem);
    attn_kernel<<<dim3(T_SEQ / 64, BHTOT), 256, attn_smem>>>(mask);

    gemm_kernel<<<gg, 256>>>(nullptr, Wo, bo, out, 0, 1);
}

// round 5
// speedup vs baseline: 2.4753x; 2.4753x over previous
#include <cuda_runtime.h>
#include <cuda_bf16.h>
#include <cstdint>

#define T_SEQ 2048
#define NFEAT 512
#define HEADS 8
#define DK 64
#define BHTOT 32
#define MTOT 8192
#define TLD 36   // smem row stride in 32-bit words (72 bf16 = 144 B)

// Scratch (static device globals). Q pre-scaled by 1/8. V stored transposed.
__device__ __nv_bfloat16 g_q_h[(size_t)BHTOT*T_SEQ*DK];
__device__ __nv_bfloat16 g_q_l[(size_t)BHTOT*T_SEQ*DK];
__device__ __nv_bfloat16 g_k_h[(size_t)BHTOT*T_SEQ*DK];
__device__ __nv_bfloat16 g_k_l[(size_t)BHTOT*T_SEQ*DK];
__device__ __nv_bfloat16 g_vt_h[(size_t)BHTOT*DK*T_SEQ];   // [bh][d][t]
__device__ __nv_bfloat16 g_vt_l[(size_t)BHTOT*DK*T_SEQ];
__device__ float g_x[(size_t)MTOT*NFEAT];                  // attn out (fp32)

// split x,y into packed bf16 hi-pair and lo-pair (residual)
static __device__ __forceinline__ void split2(float x, float y,
                                              uint32_t& hw, uint32_t& lw) {
    __nv_bfloat162 h = __floats2bfloat162_rn(x, y);
    float hx = __low2float(h), hy = __high2float(h);
    __nv_bfloat162 l = __floats2bfloat162_rn(x - hx, y - hy);
    hw = *reinterpret_cast<uint32_t*>(&h);
    lw = *reinterpret_cast<uint32_t*>(&l);
}

static __device__ __forceinline__ void mma16816(float* d, const uint32_t* a,
                                                const uint32_t* b) {
    asm volatile(
        "mma.sync.aligned.m16n8k16.row.col.f32.bf16.bf16.f32 "
        "{%0,%1,%2,%3}, {%4,%5,%6,%7}, {%8,%9}, {%0,%1,%2,%3};"
        : "+f"(d[0]), "+f"(d[1]), "+f"(d[2]), "+f"(d[3])
        : "r"(a[0]), "r"(a[1]), "r"(a[2]), "r"(a[3]), "r"(b[0]), "r"(b[1]));
}

// ---------------------------------------------------------------------------
// bf16-3x GEMM: Out[M,N] = X[M,K] @ W[N,K]^T + bias ; M=8192, N=K=512
// CTA 128x128, 256 thr (8 warps 4m x 2n), warp 32x64, k-chunk 64.
// out_sel: 0 -> Out fp32; 1 -> g_q hi/lo (x1/8); 2 -> g_k hi/lo;
//          3 -> g_vt hi/lo (transposed via smem staging)
// ---------------------------------------------------------------------------
extern __shared__ uint32_t smw[];

__global__ __launch_bounds__(256) void gemm_tc(
    const float* __restrict__ X, const float* __restrict__ W,
    const float* __restrict__ Bv, float* __restrict__ Out,
    int out_sel, int in_sel)
{
    if (in_sel) X = g_x;
    uint32_t* Ah = smw;
    uint32_t* Al = smw + 128*TLD;
    uint32_t* Bh = smw + 2*128*TLD;
    uint32_t* Bl = smw + 3*128*TLD;

    const int tid = threadIdx.x, lane = tid & 31, wid = tid >> 5;
    const int g = lane >> 2, c = lane & 3;
    const int mw = wid >> 1, nw = wid & 1;
    const int m0 = blockIdx.y * 128, n0 = blockIdx.x * 128;

    float acc[2][8][4] = {};

    for (int k0 = 0; k0 < NFEAT; k0 += 64) {
        __syncthreads();
        #pragma unroll
        for (int l = 0; l < 8; l++) {
            int idx = tid + l * 256, row = idx >> 4, c4 = idx & 15;
            float4 a = *(const float4*)&X[(size_t)(m0+row)*NFEAT + k0 + c4*4];
            uint32_t h0, l0, h1, l1;
            split2(a.x, a.y, h0, l0); split2(a.z, a.w, h1, l1);
            Ah[row*TLD + c4*2] = h0; Ah[row*TLD + c4*2 + 1] = h1;
            Al[row*TLD + c4*2] = l0; Al[row*TLD + c4*2 + 1] = l1;
            float4 w = *(const float4*)&W[(size_t)(n0+row)*NFEAT + k0 + c4*4];
            split2(w.x, w.y, h0, l0); split2(w.z, w.w, h1, l1);
            Bh[row*TLD + c4*2] = h0; Bh[row*TLD + c4*2 + 1] = h1;
            Bl[row*TLD + c4*2] = l0; Bl[row*TLD + c4*2 + 1] = l1;
        }
        __syncthreads();

        #pragma unroll
        for (int ks = 0; ks < 4; ks++) {
            uint32_t ah[2][4], alr[2][4], bhr[8][2], blr[8][2];
            #pragma unroll
            for (int mf = 0; mf < 2; mf++) {
                int rb = mw*32 + mf*16;
                ah[mf][0]  = Ah[(rb+g  )*TLD + ks*8 + c];
                ah[mf][1]  = Ah[(rb+g+8)*TLD + ks*8 + c];
                ah[mf][2]  = Ah[(rb+g  )*TLD + ks*8 + c + 4];
                ah[mf][3]  = Ah[(rb+g+8)*TLD + ks*8 + c + 4];
                alr[mf][0] = Al[(rb+g  )*TLD + ks*8 + c];
                alr[mf][1] = Al[(rb+g+8)*TLD + ks*8 + c];
                alr[mf][2] = Al[(rb+g  )*TLD + ks*8 + c + 4];
                alr[mf][3] = Al[(rb+g+8)*TLD + ks*8 + c + 4];
            }
            #pragma unroll
            for (int nf = 0; nf < 8; nf++) {
                int rb = (nw*64 + nf*8 + g)*TLD + ks*8;
                bhr[nf][0] = Bh[rb + c]; bhr[nf][1] = Bh[rb + c + 4];
                blr[nf][0] = Bl[rb + c]; blr[nf][1] = Bl[rb + c + 4];
            }
            #pragma unroll
            for (int mf = 0; mf < 2; mf++)
                #pragma unroll
                for (int nf = 0; nf < 8; nf++) {
                    mma16816(acc[mf][nf], ah[mf],  bhr[nf]);
                    mma16816(acc[mf][nf], ah[mf],  blr[nf]);
                    mma16816(acc[mf][nf], alr[mf], bhr[nf]);
                }
        }
    }

    // ---- epilogues ----
    if (out_sel == 0) {
        #pragma unroll
        for (int mf = 0; mf < 2; mf++) {
            int r0 = mw*32 + mf*16 + g;
            #pragma unroll
            for (int nf = 0; nf < 8; nf++) {
                int col = n0 + nw*64 + nf*8 + 2*c;
                float2 bb = *(const float2*)&Bv[col];
                float2 o0 = {acc[mf][nf][0] + bb.x, acc[mf][nf][1] + bb.y};
                float2 o1 = {acc[mf][nf][2] + bb.x, acc[mf][nf][3] + bb.y};
                *(float2*)&Out[(size_t)(m0+r0  )*NFEAT + col] = o0;
                *(float2*)&Out[(size_t)(m0+r0+8)*NFEAT + col] = o1;
            }
        }
    } else if (out_sel == 1 || out_sel == 2) {
        __nv_bfloat16* Oh = (out_sel == 1) ? g_q_h : g_k_h;
        __nv_bfloat16* Ol = (out_sel == 1) ? g_q_l : g_k_l;
        const float scl = (out_sel == 1) ? 0.125f : 1.0f;
        #pragma unroll
        for (int mf = 0; mf < 2; mf++)
            #pragma unroll
            for (int half = 0; half < 2; half++) {
                int m  = m0 + mw*32 + mf*16 + g + half*8;
                int bb_ = m >> 11, tt = m & (T_SEQ - 1);
                #pragma unroll
                for (int nf = 0; nf < 8; nf++) {
                    int col = nw*64 + nf*8 + 2*c;
                    int hh = (n0 + col) >> 6, d = (n0 + col) & 63;
                    float2 bb = *(const float2*)&Bv[n0 + col];
                    float v0 = (acc[mf][nf][half*2+0] + bb.x) * scl;
                    float v1 = (acc[mf][nf][half*2+1] + bb.y) * scl;
                    uint32_t hw, lw; split2(v0, v1, hw, lw);
                    size_t widx = (((size_t)(bb_*HEADS+hh)*T_SEQ + tt)*DK + d) >> 1;
                    ((uint32_t*)Oh)[widx] = hw;
                    ((uint32_t*)Ol)[widx] = lw;
                }
            }
    } else {
        // V: transpose to [bh][d][t] through smem, hi+lo staged together
        __syncthreads();
        __nv_bfloat16* Tsh = (__nv_bfloat16*)smw;                       // [128n][136]
        __nv_bfloat16* Tsl = (__nv_bfloat16*)((char*)smw + 128*272);
        #pragma unroll
        for (int mf = 0; mf < 2; mf++)
            #pragma unroll
            for (int half = 0; half < 2; half++) {
                int t_loc = mw*32 + mf*16 + g + half*8;
                #pragma unroll
                for (int nf = 0; nf < 8; nf++) {
                    int col = nw*64 + nf*8 + 2*c;
                    float2 bb = *(const float2*)&Bv[n0 + col];
                    float v0 = acc[mf][nf][half*2+0] + bb.x;
                    float v1 = acc[mf][nf][half*2+1] + bb.y;
                    __nv_bfloat162 h2 = __floats2bfloat162_rn(v0, v1);
                    __nv_bfloat162 l2 = __floats2bfloat162_rn(
                        v0 - __low2float(h2), v1 - __high2float(h2));
                    Tsh[(size_t)(col  )*136 + t_loc] = h2.x;
                    Tsh[(size_t)(col+1)*136 + t_loc] = h2.y;
                    Tsl[(size_t)(col  )*136 + t_loc] = l2.x;
                    Tsl[(size_t)(col+1)*136 + t_loc] = l2.y;
                }
            }
        __syncthreads();
        int bb_ = m0 >> 11, tt0 = m0 & (T_SEQ - 1);
        #pragma unroll
        for (int l = 0; l < 8; l++) {
            int idx = tid + l * 256, n = idx >> 4, j = idx & 15;
            int hh = (n0 >> 6) + (n >> 6), d = n & 63;
            size_t go = ((size_t)(bb_*HEADS + hh)*DK + d)*T_SEQ + tt0 + j*8;
            *(uint4*)&g_vt_h[go] = *(uint4*)((char*)Tsh + (size_t)n*272 + j*16);
            *(uint4*)&g_vt_l[go] = *(uint4*)((char*)Tsl + (size_t)n*272 + j*16);
        }
    }
}

// ---------------------------------------------------------------------------
// bf16-3x attention. CTA = (bh, 128-q tile), 256 thr (4m x 2n warps).
// Key tile 64, 32 tiles covering T=2048. Max-free softmax, O in registers.
// ---------------------------------------------------------------------------
#define AQH 0
#define AQL 18432
#define AKH 36864
#define AKL 46080
#define AVH 55296
#define AVL 64512
#define APH 73728
#define APL 92160
#define AMB 110592
#define ALS 110848
#define ATTN_SMEM 111872

__global__ __launch_bounds__(256) void attn_tc(const int* __restrict__ mask)
{
    extern __shared__ char sm[];
    float* mbuf = (float*)(sm + AMB);
    float* lsm  = (float*)(sm + ALS);
    const uint32_t* Qhw = (const uint32_t*)(sm + AQH);
    const uint32_t* Qlw = (const uint32_t*)(sm + AQL);
    const uint32_t* Khw = (const uint32_t*)(sm + AKH);
    const uint32_t* Klw = (const uint32_t*)(sm + AKL);
    const uint32_t* Vhw = (const uint32_t*)(sm + AVH);
    const uint32_t* Vlw = (const uint32_t*)(sm + AVL);
    uint32_t* Phw = (uint32_t*)(sm + APH);
    uint32_t* Plw = (uint32_t*)(sm + APL);

    const int tid = threadIdx.x, lane = tid & 31, wid = tid >> 5;
    const int g = lane >> 2, c = lane & 3;
    const int mw = wid >> 1, nw = wid & 1;
    const int bh = blockIdx.y, b = bh >> 3, h = bh & 7;
    const int q0 = blockIdx.x * 128;

    // Q tile (once): 128 rows x 64 bf16, hi+lo
    #pragma unroll
    for (int l = 0; l < 4; l++) {
        int idx = tid + l * 256, row = idx >> 3, j = idx & 7;
        size_t gsrc = ((size_t)bh*T_SEQ + q0 + row)*DK + j*8;
        *(uint4*)(sm + AQH + row*144 + j*16) = *(const uint4*)&g_q_h[gsrc];
        *(uint4*)(sm + AQL + row*144 + j*16) = *(const uint4*)&g_q_l[gsrc];
    }

    float oacc[2][4][4] = {};
    float lacc[2][2] = {};

    for (int it = 0; it < T_SEQ / 64; it++) {   // 32 tiles = full sequence
        const int kt = it * 64;
        __syncthreads();
        #pragma unroll
        for (int l = 0; l < 2; l++) {
            int idx = tid + l * 256, row = idx >> 3, j = idx & 7;
            size_t ksrc = ((size_t)bh*T_SEQ + kt + row)*DK + j*8;
            *(uint4*)(sm + AKH + row*144 + j*16) = *(const uint4*)&g_k_h[ksrc];
            *(uint4*)(sm + AKL + row*144 + j*16) = *(const uint4*)&g_k_l[ksrc];
            size_t vsrc = ((size_t)bh*DK + row)*T_SEQ + kt + j*8;
            *(uint4*)(sm + AVH + row*144 + j*16) = *(const uint4*)&g_vt_h[vsrc];
            *(uint4*)(sm + AVL + row*144 + j*16) = *(const uint4*)&g_vt_l[vsrc];
        }
        if (tid < 64) mbuf[tid] = (float)mask[b*T_SEQ + kt + tid];
        __syncthreads();

        // ---- S = Q K^T ----
        float sacc[2][4][4] = {};
        #pragma unroll
        for (int ks = 0; ks < 4; ks++) {
            uint32_t ah[2][4], alr[2][4], bhr[4][2], blr[4][2];
            #pragma unroll
            for (int mf = 0; mf < 2; mf++) {
                int rb = mw*32 + mf*16;
                ah[mf][0]  = Qhw[(rb+g  )*TLD + ks*8 + c];
                ah[mf][1]  = Qhw[(rb+g+8)*TLD + ks*8 + c];
                ah[mf][2]  = Qhw[(rb+g  )*TLD + ks*8 + c + 4];
                ah[mf][3]  = Qhw[(rb+g+8)*TLD + ks*8 + c + 4];
                alr[mf][0] = Qlw[(rb+g  )*TLD + ks*8 + c];
                alr[mf][1] = Qlw[(rb+g+8)*TLD + ks*8 + c];
                alr[mf][2] = Qlw[(rb+g  )*TLD + ks*8 + c + 4];
                alr[mf][3] = Qlw[(rb+g+8)*TLD + ks*8 + c + 4];
            }
            #pragma unroll
            for (int nf = 0; nf < 4; nf++) {
                int rb = (nw*32 + nf*8 + g)*TLD + ks*8;
                bhr[nf][0] = Khw[rb + c]; bhr[nf][1] = Khw[rb + c + 4];
                blr[nf][0] = Klw[rb + c]; blr[nf][1] = Klw[rb + c + 4];
            }
            #pragma unroll
            for (int mf = 0; mf < 2; mf++)
                #pragma unroll
                for (int nf = 0; nf < 4; nf++) {
                    mma16816(sacc[mf][nf], ah[mf],  bhr[nf]);
                    mma16816(sacc[mf][nf], ah[mf],  blr[nf]);
                    mma16816(sacc[mf][nf], alr[mf], bhr[nf]);
                }
        }

        // ---- exp + mask + row-sum partials, P -> smem (hi/lo) ----
        #pragma unroll
        for (int mf = 0; mf < 2; mf++)
            #pragma unroll
            for (int nf = 0; nf < 4; nf++) {
                int colb = nw*32 + nf*8 + 2*c;
                float m0v = mbuf[colb], m1v = mbuf[colb + 1];
                float e0 = __expf(sacc[mf][nf][0]) * m0v;
                float e1 = __expf(sacc[mf][nf][1]) * m1v;
                float e2 = __expf(sacc[mf][nf][2]) * m0v;
                float e3 = __expf(sacc[mf][nf][3]) * m1v;
                lacc[mf][0] += e0 + e1;
                lacc[mf][1] += e2 + e3;
                int r0 = mw*32 + mf*16 + g;
                int wc = nw*16 + nf*4 + c;
                uint32_t hw, lw;
                split2(e0, e1, hw, lw);
                Phw[r0*TLD + wc] = hw; Plw[r0*TLD + wc] = lw;
                split2(e2, e3, hw, lw);
                Phw[(r0+8)*TLD + wc] = hw; Plw[(r0+8)*TLD + wc] = lw;
            }
        __syncthreads();

        // ---- O += P V ----
        #pragma unroll
        for (int ks = 0; ks < 4; ks++) {
            uint32_t ah[2][4], alr[2][4], bhr[4][2], blr[4][2];
            #pragma unroll
            for (int mf = 0; mf < 2; mf++) {
                int rb = mw*32 + mf*16;
                ah[mf][0]  = Phw[(rb+g  )*TLD + ks*8 + c];
                ah[mf][1]  = Phw[(rb+g+8)*TLD + ks*8 + c];
                ah[mf][2]  = Phw[(rb+g  )*TLD + ks*8 + c + 4];
                ah[mf][3]  = Phw[(rb+g+8)*TLD + ks*8 + c + 4];
                alr[mf][0] = Plw[(rb+g  )*TLD + ks*8 + c];
                alr[mf][1] = Plw[(rb+g+8)*TLD + ks*8 + c];
                alr[mf][2] = Plw[(rb+g  )*TLD + ks*8 + c + 4];
                alr[mf][3] = Plw[(rb+g+8)*TLD + ks*8 + c + 4];
            }
            #pragma unroll
            for (int nf = 0; nf < 4; nf++) {
                int rb = (nw*32 + nf*8 + g)*TLD + ks*8;
                bhr[nf][0] = Vhw[rb + c]; bhr[nf][1] = Vhw[rb + c + 4];
                blr[nf][0] = Vlw[rb + c]; blr[nf][1] = Vlw[rb + c + 4];
            }
            #pragma unroll
            for (int mf = 0; mf < 2; mf++)
                #pragma unroll
                for (int nf = 0; nf < 4; nf++) {
                    mma16816(oacc[mf][nf], ah[mf],  bhr[nf]);
                    mma16816(oacc[mf][nf], ah[mf],  blr[nf]);
                    mma16816(oacc[mf][nf], alr[mf], bhr[nf]);
                }
        }
    }

    // ---- reduce l across quad (c lanes), then across the 2 n-warps ----
    #pragma unroll
    for (int mf = 0; mf < 2; mf++)
        #pragma unroll
        for (int hf = 0; hf < 2; hf++) {
            float lv = lacc[mf][hf];
            lv += __shfl_xor_sync(0xffffffffu, lv, 1);
            lv += __shfl_xor_sync(0xffffffffu, lv, 2);
            lacc[mf][hf] = lv;
        }
    if (c == 0) {
        #pragma unroll
        for (int mf = 0; mf < 2; mf++) {
            lsm[nw*128 + mw*32 + mf*16 + g]     = lacc[mf][0];
            lsm[nw*128 + mw*32 + mf*16 + g + 8] = lacc[mf][1];
        }
    }
    __syncthreads();
    #pragma unroll
    for (int mf = 0; mf < 2; mf++)
        #pragma unroll
        for (int half = 0; half < 2; half++) {
            int row = mw*32 + mf*16 + g + half*8;
            float lt = lsm[row] + lsm[128 + row];
            float inv = (lt > 0.f) ? 1.f / (lt * (1.f + 1e-8f)) : 0.f;
            #pragma unroll
            for (int nf = 0; nf < 4; nf++) {
                int col = nw*32 + nf*8 + 2*c;
                float2 o = {oacc[mf][nf][half*2+0] * inv,
                            oacc[mf][nf][half*2+1] * inv};
                *(float2*)&g_x[(size_t)(b*T_SEQ + q0 + row)*NFEAT + h*DK + col] = o;
            }
        }
}

// ---------------------------------------------------------------------------
extern "C" void kernel_launch(void* const* d_in, const int* in_sizes, int n_in,
                              void* d_out, int out_size)
{
    const float* query = (const float*)d_in[0];
    const float* key_  = (const float*)d_in[1];
    const float* value = (const float*)d_in[2];
    const int*   mask  = (const int*)d_in[3];
    const float* Wq = (const float*)d_in[4];
    const float* bq = (const float*)d_in[5];
    const float* Wk = (const float*)d_in[6];
    const float* bk = (const float*)d_in[7];
    const float* Wv = (const float*)d_in[8];
    const float* bv = (const float*)d_in[9];
    const float* Wo = (const float*)d_in[10];
    const float* bo = (const float*)d_in[11];
    float* out = (float*)d_out;

    const int GS = 4 * 128 * TLD * (int)sizeof(uint32_t);   // 73728
    cudaFuncSetAttribute(gemm_tc, cudaFuncAttributeMaxDynamicSharedMemorySize, GS);
    cudaFuncSetAttribute(attn_tc, cudaFuncAttributeMaxDynamicSharedMemorySize,
                         ATTN_SMEM);

    dim3 gg(NFEAT / 128, MTOT / 128);   // (4, 64)

    gemm_tc<<<gg, 256, GS>>>(query, Wq, bq, nullptr, 1, 0);
    gemm_tc<<<gg, 256, GS>>>(key_,  Wk, bk, nullptr, 2, 0);
    gemm_tc<<<gg, 256, GS>>>(value, Wv, bv, nullptr, 3, 0);

    attn_tc<<<dim3(T_SEQ / 128, BHTOT), 256, ATTN_SMEM>>>(mask);

    gemm_tc<<<gg, 256, GS>>>(nullptr, Wo, bo, out, 0, 1);
}